// round 1
// baseline (speedup 1.0000x reference)
#include <cuda_runtime.h>
#include <cstddef>
#include <math.h>

#define N_TOK 4096
#define DIM 768
#define HEADS 12
#define HD 64          // head dim
#define QKV_COLS (3 * DIM)   // 2304

// Scratch (allocation-free rule: __device__ globals)
__device__ float g_qkv[(size_t)N_TOK * QKV_COLS];   // [4096, 2304]
__device__ float g_attn[(size_t)N_TOK * DIM];       // [4096, 768]

// ---------------------------------------------------------------------------
// SGEMM: C[M,N] = A[M,K] @ B[K,N] (+ bias[N] if bias != nullptr)
// BM=BN=128, BK=8, 256 threads, 8x8 microtile. M,N multiples of 128; K of 8.
// ---------------------------------------------------------------------------
__global__ __launch_bounds__(256) void sgemm_kernel(
    const float* __restrict__ A, const float* __restrict__ B,
    const float* __restrict__ bias, float* __restrict__ C,
    int M, int N, int K) {
  __shared__ float As[8][128];
  __shared__ float Bs[8][128];

  const int tid = threadIdx.x;
  const int ty = tid >> 4;        // 0..15
  const int tx = tid & 15;        // 0..15

  const int arow = tid >> 1;             // 0..127
  const int acol = (tid & 1) * 4;        // 0 or 4
  const int browl = tid >> 5;            // 0..7
  const int bcoll = (tid & 31) * 4;      // 0..124

  const float* Ab = A + (size_t)blockIdx.y * 128 * K;
  const float* Bb = B + (size_t)blockIdx.x * 128;

  float acc[8][8];
  #pragma unroll
  for (int i = 0; i < 8; i++)
    #pragma unroll
    for (int j = 0; j < 8; j++) acc[i][j] = 0.f;

  for (int k0 = 0; k0 < K; k0 += 8) {
    float4 a4 = *(const float4*)(Ab + (size_t)arow * K + k0 + acol);
    As[acol + 0][arow] = a4.x;
    As[acol + 1][arow] = a4.y;
    As[acol + 2][arow] = a4.z;
    As[acol + 3][arow] = a4.w;
    *(float4*)&Bs[browl][bcoll] =
        *(const float4*)(Bb + (size_t)(k0 + browl) * N + bcoll);
    __syncthreads();

    #pragma unroll
    for (int k = 0; k < 8; k++) {
      float ar[8], br[8];
      *(float4*)&ar[0] = *(const float4*)&As[k][ty * 8];
      *(float4*)&ar[4] = *(const float4*)&As[k][ty * 8 + 4];
      *(float4*)&br[0] = *(const float4*)&Bs[k][tx * 8];
      *(float4*)&br[4] = *(const float4*)&Bs[k][tx * 8 + 4];
      #pragma unroll
      for (int i = 0; i < 8; i++)
        #pragma unroll
        for (int j = 0; j < 8; j++) acc[i][j] += ar[i] * br[j];
    }
    __syncthreads();
  }

  const int crow0 = blockIdx.y * 128 + ty * 8;
  const int ccol0 = blockIdx.x * 128 + tx * 8;
  float bv[8];
  if (bias) {
    #pragma unroll
    for (int j = 0; j < 8; j++) bv[j] = bias[ccol0 + j];
  } else {
    #pragma unroll
    for (int j = 0; j < 8; j++) bv[j] = 0.f;
  }
  #pragma unroll
  for (int i = 0; i < 8; i++) {
    float4 v0, v1;
    v0.x = acc[i][0] + bv[0]; v0.y = acc[i][1] + bv[1];
    v0.z = acc[i][2] + bv[2]; v0.w = acc[i][3] + bv[3];
    v1.x = acc[i][4] + bv[4]; v1.y = acc[i][5] + bv[5];
    v1.z = acc[i][6] + bv[6]; v1.w = acc[i][7] + bv[7];
    float* crow = C + (size_t)(crow0 + i) * N + ccol0;
    *(float4*)crow = v0;
    *(float4*)(crow + 4) = v1;
  }
}

// ---------------------------------------------------------------------------
// Flash attention (unscaled dots, per reference).
// Grid: (N_TOK/64, HEADS). Block: 256 threads = 16x16.
// Thread (ty,tx) owns rows {ty+16a} and cols/dims {tx+16b}, a,b in 0..3.
// Dynamic smem layout (floats):
//   Qs [64][64]  Ks [64][68]  Vs [64][64]  Ss [64][68]
// Pitches chosen for conflict-free K reads (stride-16-row LDS.128) and
// conflict-free S writes.
// ---------------------------------------------------------------------------
#define QS_PITCH 64
#define KS_PITCH 68
#define VS_PITCH 64
#define SS_PITCH 68
#define SMEM_ATTN ((64 * (QS_PITCH + KS_PITCH + VS_PITCH + SS_PITCH)) * 4)

__global__ __launch_bounds__(256) void flash_attn_kernel(
    const float* __restrict__ qkv, float* __restrict__ attn_out) {
  extern __shared__ float sm[];
  float* Qs = sm;                       // 64*64
  float* Ks = Qs + 64 * QS_PITCH;       // 64*68
  float* Vs = Ks + 64 * KS_PITCH;       // 64*64
  float* Ss = Vs + 64 * VS_PITCH;       // 64*68

  const int qblk = blockIdx.x;
  const int h = blockIdx.y;
  const int tid = threadIdx.x;
  const int ty = tid >> 4;   // 0..15
  const int tx = tid & 15;   // 0..15
  const int qbase = qblk * 64;
  const int hoff = h * HD;

  const int ldr = tid >> 4;
  const int ldc = (tid & 15) * 4;

  // Load Q tile once
  #pragma unroll
  for (int rr = 0; rr < 64; rr += 16) {
    *(float4*)(Qs + (ldr + rr) * QS_PITCH + ldc) =
        *(const float4*)(qkv + (size_t)(qbase + ldr + rr) * QKV_COLS + hoff + ldc);
  }

  float m[4], l[4], O[4][4];
  #pragma unroll
  for (int a = 0; a < 4; a++) {
    m[a] = -INFINITY;
    l[a] = 0.f;
    #pragma unroll
    for (int b = 0; b < 4; b++) O[a][b] = 0.f;
  }

  for (int j = 0; j < N_TOK / 64; j++) {
    const int kvbase = j * 64;
    // Load K and V tiles
    #pragma unroll
    for (int rr = 0; rr < 64; rr += 16) {
      const float* src =
          qkv + (size_t)(kvbase + ldr + rr) * QKV_COLS + hoff + ldc;
      *(float4*)(Ks + (ldr + rr) * KS_PITCH + ldc) = *(const float4*)(src + DIM);
      *(float4*)(Vs + (ldr + rr) * VS_PITCH + ldc) = *(const float4*)(src + 2 * DIM);
    }
    __syncthreads();

    // S = Q @ K^T (4x4 microtile, k vectorized by 4)
    float s[4][4];
    #pragma unroll
    for (int a = 0; a < 4; a++)
      #pragma unroll
      for (int b = 0; b < 4; b++) s[a][b] = 0.f;

    #pragma unroll
    for (int k = 0; k < HD; k += 4) {
      float4 qv[4], kv4[4];
      #pragma unroll
      for (int a = 0; a < 4; a++)
        qv[a] = *(const float4*)(Qs + (ty + 16 * a) * QS_PITCH + k);
      #pragma unroll
      for (int b = 0; b < 4; b++)
        kv4[b] = *(const float4*)(Ks + (tx + 16 * b) * KS_PITCH + k);
      #pragma unroll
      for (int a = 0; a < 4; a++)
        #pragma unroll
        for (int b = 0; b < 4; b++) {
          s[a][b] += qv[a].x * kv4[b].x;
          s[a][b] += qv[a].y * kv4[b].y;
          s[a][b] += qv[a].z * kv4[b].z;
          s[a][b] += qv[a].w * kv4[b].w;
        }
    }

    // Online softmax per row (16-lane reduction across tx; lanes with the
    // same ty are 16 consecutive lanes, xor 1/2/4/8 stays in-group).
    #pragma unroll
    for (int a = 0; a < 4; a++) {
      float mt = fmaxf(fmaxf(s[a][0], s[a][1]), fmaxf(s[a][2], s[a][3]));
      #pragma unroll
      for (int w = 1; w < 16; w <<= 1)
        mt = fmaxf(mt, __shfl_xor_sync(0xffffffffu, mt, w));
      const float mn = fmaxf(m[a], mt);
      const float alpha = __expf(m[a] - mn);
      float p[4];
      float rs = 0.f;
      #pragma unroll
      for (int b = 0; b < 4; b++) {
        p[b] = __expf(s[a][b] - mn);
        rs += p[b];
      }
      #pragma unroll
      for (int w = 1; w < 16; w <<= 1)
        rs += __shfl_xor_sync(0xffffffffu, rs, w);
      l[a] = alpha * l[a] + rs;
      m[a] = mn;
      #pragma unroll
      for (int b = 0; b < 4; b++) {
        O[a][b] *= alpha;
        Ss[(ty + 16 * a) * SS_PITCH + tx + 16 * b] = p[b];
      }
    }
    __syncthreads();

    // O += P @ V
    #pragma unroll
    for (int c = 0; c < 64; c += 4) {
      float4 pvv[4];
      #pragma unroll
      for (int a = 0; a < 4; a++)
        pvv[a] = *(const float4*)(Ss + (ty + 16 * a) * SS_PITCH + c);
      float pr[4][4];
      #pragma unroll
      for (int a = 0; a < 4; a++) {
        pr[a][0] = pvv[a].x; pr[a][1] = pvv[a].y;
        pr[a][2] = pvv[a].z; pr[a][3] = pvv[a].w;
      }
      #pragma unroll
      for (int cc = 0; cc < 4; cc++) {
        float vv[4];
        #pragma unroll
        for (int b = 0; b < 4; b++)
          vv[b] = Vs[(c + cc) * VS_PITCH + tx + 16 * b];
        #pragma unroll
        for (int a = 0; a < 4; a++)
          #pragma unroll
          for (int b = 0; b < 4; b++) O[a][b] += pr[a][cc] * vv[b];
      }
    }
    __syncthreads();
  }

  // Epilogue: normalize and write [4096, 768] slice for this head
  #pragma unroll
  for (int a = 0; a < 4; a++) {
    const float inv = 1.f / l[a];
    const int row = qbase + ty + 16 * a;
    #pragma unroll
    for (int b = 0; b < 4; b++)
      attn_out[(size_t)row * DIM + hoff + tx + 16 * b] = O[a][b] * inv;
  }
}

// ---------------------------------------------------------------------------
extern "C" void kernel_launch(void* const* d_in, const int* in_sizes, int n_in,
                              void* d_out, int out_size) {
  const float* x = (const float*)d_in[0];      // [1, 4096, 768]
  const float* Wqkv = (const float*)d_in[1];   // [768, 2304]
  const float* Wout = (const float*)d_in[2];   // [768, 768]
  const float* bout = (const float*)d_in[3];   // [768]
  float* out = (float*)d_out;                  // [1, 4096, 768]

  float* qkv = nullptr;
  float* attn = nullptr;
  cudaGetSymbolAddress((void**)&qkv, g_qkv);
  cudaGetSymbolAddress((void**)&attn, g_attn);

  cudaFuncSetAttribute(flash_attn_kernel,
                       cudaFuncAttributeMaxDynamicSharedMemorySize, SMEM_ATTN);

  // 1) qkv = x @ W_qkv          [4096,768] x [768,2304]
  sgemm_kernel<<<dim3(QKV_COLS / 128, N_TOK / 128), 256>>>(
      x, Wqkv, nullptr, qkv, N_TOK, QKV_COLS, DIM);

  // 2) per-head flash attention -> attn [4096, 768]
  flash_attn_kernel<<<dim3(N_TOK / 64, HEADS), 256, SMEM_ATTN>>>(qkv, attn);

  // 3) out = attn @ W_out + b_out
  sgemm_kernel<<<dim3(DIM / 128, N_TOK / 128), 256>>>(
      attn, Wout, bout, out, N_TOK, DIM, DIM);
}